// round 6
// baseline (speedup 1.0000x reference)
#include <cuda_runtime.h>
#include <cstdint>

// Problem constants
#define BB   8
#define LL   512
#define DD   1024
#define SS   6144
#define NSPAN (BB * SS)    // 49152 spans
#define MM   (BB * LL)     // 4096 GEMM rows
#define LP1  (LL + 1)      // 513 prefix rows
#define NT   8             // prefix tiles along t
#define TW   (LL / NT)     // 64 timesteps per tile

// Scratch (device globals: no allocation allowed)
__device__ float g_p[MM * DD];          // p = h @ W^T          (16 MB)
__device__ float g_g[BB * LP1 * DD];    // prefix sums of p     (16.8 MB)
__device__ float g_part[BB * NT * DD];  // per-tile partial sums (256 KB)

__device__ int   g_vspan[NSPAN];        // valid: output row (span id)
__device__ int   g_vgs[NSPAN];          // valid: G row of start
__device__ int   g_vge[NSPAN];          // valid: G row of end+1
__device__ float g_vinv[NSPAN];         // valid: 1/count
__device__ int   g_vcount;
__device__ int   g_invlist[NSPAN];      // invalid span ids
__device__ int   g_invcount;

// ---------------------------------------------------------------------------
// helpers
// ---------------------------------------------------------------------------
__device__ __forceinline__ float tf32rna(float x) {
    uint32_t u;
    asm("cvt.rna.tf32.f32 %0, %1;" : "=r"(u) : "f"(x));
    return __uint_as_float(u);
}

__device__ __forceinline__ void mma_tf32(float c[4], const uint32_t a[4], const uint32_t b[2]) {
    asm volatile(
        "mma.sync.aligned.m16n8k8.row.col.f32.tf32.tf32.f32 "
        "{%0,%1,%2,%3}, {%4,%5,%6,%7}, {%8,%9}, {%0,%1,%2,%3};"
        : "+f"(c[0]), "+f"(c[1]), "+f"(c[2]), "+f"(c[3])
        : "r"(a[0]), "r"(a[1]), "r"(a[2]), "r"(a[3]),
          "r"(b[0]), "r"(b[1]));
}

__device__ __forceinline__ int detect_is32(const int* idx_words) {
    // int64: odd 32-bit words are the zero high halves of values < 512.
    // int32: odd words are 'end' values -- 64 zeros is impossible.
    int any = 0;
    #pragma unroll
    for (int j = 0; j < 64; j++) any |= idx_words[2 * j + 1];
    return (any != 0) ? 1 : 0;
}

// ---------------------------------------------------------------------------
// Kernel 1: GEMM (unchanged known-good version, 65.6us)
// ---------------------------------------------------------------------------
#define BM 128
#define BN 128
#define BK 32
#define KPAD 36

__global__ void __launch_bounds__(256)
gemm_tf32_kernel(const float* __restrict__ A,
                 const float* __restrict__ Wm,
                 float* __restrict__ P)
{
    __shared__ float As[BM * KPAD];
    __shared__ float Bs[BN * KPAD];

    const int tid  = threadIdx.x;
    const int warp = tid >> 5;
    const int lane = tid & 31;
    const int wm   = warp >> 1;
    const int wn   = warp & 1;
    const int m0   = blockIdx.x * BM;
    const int n0   = blockIdx.y * BN;

    const int lr = tid >> 3;
    const int lc = (tid & 7) * 4;

    const float* Ag = A  + (size_t)(m0 + lr) * DD + lc;
    const float* Bg = Wm + (size_t)(n0 + lr) * DD + lc;

    float acc[2][8][4];
    #pragma unroll
    for (int mt = 0; mt < 2; mt++)
        #pragma unroll
        for (int nt = 0; nt < 8; nt++)
            #pragma unroll
            for (int r = 0; r < 4; r++) acc[mt][nt][r] = 0.0f;

    float4 ra[4], rb[4];
    #pragma unroll
    for (int j = 0; j < 4; j++) {
        ra[j] = *(const float4*)(Ag + (size_t)j * 32 * DD);
        rb[j] = *(const float4*)(Bg + (size_t)j * 32 * DD);
    }

    const int NKT = DD / BK;
    for (int kt = 0; kt < NKT; kt++) {
        #pragma unroll
        for (int j = 0; j < 4; j++) {
            float4 a = ra[j], b = rb[j];
            a.x = tf32rna(a.x); a.y = tf32rna(a.y); a.z = tf32rna(a.z); a.w = tf32rna(a.w);
            b.x = tf32rna(b.x); b.y = tf32rna(b.y); b.z = tf32rna(b.z); b.w = tf32rna(b.w);
            *(float4*)(&As[(lr + j * 32) * KPAD + lc]) = a;
            *(float4*)(&Bs[(lr + j * 32) * KPAD + lc]) = b;
        }
        __syncthreads();

        if (kt + 1 < NKT) {
            const int ko = (kt + 1) * BK;
            #pragma unroll
            for (int j = 0; j < 4; j++) {
                ra[j] = *(const float4*)(Ag + (size_t)j * 32 * DD + ko);
                rb[j] = *(const float4*)(Bg + (size_t)j * 32 * DD + ko);
            }
        }

        #pragma unroll
        for (int ks = 0; ks < 4; ks++) {
            const int k0 = ks * 8 + (lane & 3);
            const int rA = wm * 32 + (lane >> 2);

            uint32_t af[2][4];
            #pragma unroll
            for (int mt = 0; mt < 2; mt++) {
                const int r = rA + mt * 16;
                af[mt][0] = __float_as_uint(As[r       * KPAD + k0]);
                af[mt][1] = __float_as_uint(As[(r + 8) * KPAD + k0]);
                af[mt][2] = __float_as_uint(As[r       * KPAD + k0 + 4]);
                af[mt][3] = __float_as_uint(As[(r + 8) * KPAD + k0 + 4]);
            }
            uint32_t bf[8][2];
            #pragma unroll
            for (int nt = 0; nt < 8; nt++) {
                const int n = wn * 64 + nt * 8 + (lane >> 2);
                bf[nt][0] = __float_as_uint(Bs[n * KPAD + k0]);
                bf[nt][1] = __float_as_uint(Bs[n * KPAD + k0 + 4]);
            }
            #pragma unroll
            for (int mt = 0; mt < 2; mt++)
                #pragma unroll
                for (int nt = 0; nt < 8; nt++)
                    mma_tf32(acc[mt][nt], af[mt], bf[nt]);
        }
        __syncthreads();
    }

    const int mrow = m0 + wm * 32 + (lane >> 2);
    const int ncol = n0 + wn * 64 + (lane & 3) * 2;
    #pragma unroll
    for (int mt = 0; mt < 2; mt++) {
        #pragma unroll
        for (int nt = 0; nt < 8; nt++) {
            const int r = mrow + mt * 16;
            const int c = ncol + nt * 8;
            *(float2*)(&P[(size_t)r       * DD + c]) = make_float2(acc[mt][nt][0], acc[mt][nt][1]);
            *(float2*)(&P[(size_t)(r + 8) * DD + c]) = make_float2(acc[mt][nt][2], acc[mt][nt][3]);
        }
    }
}

// ---------------------------------------------------------------------------
// Kernel 2a/2b: two-pass prefix sums (unchanged, ~8us)
// ---------------------------------------------------------------------------
__global__ void __launch_bounds__(256)
prefix_partial_kernel(const float* __restrict__ P, float* __restrict__ part)
{
    const int gidx = blockIdx.x * blockDim.x + threadIdx.x;
    const int e    = gidx & (DD - 1);
    const int tile = (gidx >> 10) & (NT - 1);
    const int b    = gidx >> 13;

    const float* p = P + ((size_t)b * LL + tile * TW) * DD + e;
    float s = 0.0f;
    #pragma unroll
    for (int j = 0; j < TW; j++) s += p[(size_t)j * DD];
    part[((size_t)b * NT + tile) * DD + e] = s;
}

__global__ void __launch_bounds__(256)
prefix_scan_kernel(const float* __restrict__ P,
                   const float* __restrict__ part,
                   float* __restrict__ G)
{
    const int gidx = blockIdx.x * blockDim.x + threadIdx.x;
    const int e    = gidx & (DD - 1);
    const int tile = (gidx >> 10) & (NT - 1);
    const int b    = gidx >> 13;

    float c = 0.0f;
    for (int t = 0; t < tile; t++)
        c += part[((size_t)b * NT + t) * DD + e];

    const float* p = P + ((size_t)b * LL + tile * TW) * DD + e;
    float*       g = G + ((size_t)b * LP1 + tile * TW) * DD + e;

    if (tile == 0) g[0] = 0.0f;

    #pragma unroll 8
    for (int j = 0; j < TW; j++) {
        c += p[(size_t)j * DD];
        g[(size_t)(j + 1) * DD] = c;
    }
}

// ---------------------------------------------------------------------------
// Kernel D: decode spans into compact valid/invalid lists (2 atomic counters).
// Also resets counters via the first thread trick is NOT safe across blocks,
// so a tiny init kernel zeroes them first.
// ---------------------------------------------------------------------------
__global__ void init_kernel()
{
    g_vcount = 0;
    g_invcount = 0;
}

__global__ void __launch_bounds__(256)
decode_kernel(const int* __restrict__ idx_words)
{
    __shared__ int s_is32;
    if (threadIdx.x == 0) s_is32 = detect_is32(idx_words);
    __syncthreads();

    const int span = blockIdx.x * blockDim.x + threadIdx.x;  // < NSPAN
    const int b    = span / SS;

    int w0, w1;
    if (s_is32) {
        w0 = idx_words[2 * span];
        w1 = idx_words[2 * span + 1];
    } else {
        w0 = idx_words[4 * span];
        w1 = idx_words[4 * span + 2];
    }
    const int s0 = min(max(w0, 0), LL - 1);
    const int e0 = min(max(w1, 0), LL - 1);

    if (s0 <= e0) {
        const int p = atomicAdd(&g_vcount, 1);
        g_vspan[p] = span;
        g_vgs[p]   = b * LP1 + s0;
        g_vge[p]   = b * LP1 + e0 + 1;
        g_vinv[p]  = 1.0f / (float)(e0 - s0 + 1);
    } else {
        const int p = atomicAdd(&g_invcount, 1);
        g_invlist[p] = span;
    }
}

// ---------------------------------------------------------------------------
// Epilogue A: valid spans. One block per list entry; blocks past the count
// exit immediately. out = relu((ge - gs) * inv + bias)
// ---------------------------------------------------------------------------
__global__ void __launch_bounds__(256)
epi_valid_kernel(const float* __restrict__ G,
                 const float* __restrict__ bias,
                 float* __restrict__ out)
{
    const int i = blockIdx.x;
    if (i >= g_vcount) return;

    const int   orow = g_vspan[i];
    const int   gsr  = g_vgs[i];
    const int   ger  = g_vge[i];
    const float inv  = g_vinv[i];

    const int d = threadIdx.x * 4;
    float4 a  = *(const float4*)(G + (size_t)ger * DD + d);
    float4 c  = *(const float4*)(G + (size_t)gsr * DD + d);
    float4 bb = *(const float4*)(bias + d);

    float4 o;
    o.x = fmaxf(fmaf(a.x - c.x, inv, bb.x), 0.0f);
    o.y = fmaxf(fmaf(a.y - c.y, inv, bb.y), 0.0f);
    o.z = fmaxf(fmaf(a.z - c.z, inv, bb.z), 0.0f);
    o.w = fmaxf(fmaf(a.w - c.w, inv, bb.w), 0.0f);

    *(float4*)(out + (size_t)orow * DD + d) = o;
}

// ---------------------------------------------------------------------------
// Epilogue B: invalid spans -> relu(bias). One block per list entry.
// ---------------------------------------------------------------------------
__global__ void __launch_bounds__(256)
epi_invalid_kernel(const float* __restrict__ bias, float* __restrict__ out)
{
    const int i = blockIdx.x;
    if (i >= g_invcount) return;

    const int d = threadIdx.x * 4;
    float4 bb = *(const float4*)(bias + d);
    float4 o;
    o.x = fmaxf(bb.x, 0.0f);
    o.y = fmaxf(bb.y, 0.0f);
    o.z = fmaxf(bb.z, 0.0f);
    o.w = fmaxf(bb.w, 0.0f);

    const int row = g_invlist[i];
    *(float4*)(out + (size_t)row * DD + d) = o;
}

// ---------------------------------------------------------------------------
// launch
// ---------------------------------------------------------------------------
extern "C" void kernel_launch(void* const* d_in, const int* in_sizes, int n_in,
                              void* d_out, int out_size)
{
    const float* h   = nullptr;
    const void*  idx = nullptr;
    const float* W   = nullptr;
    const float* bia = nullptr;
    for (int i = 0; i < n_in; i++) {
        switch (in_sizes[i]) {
            case BB * LL * DD:   h   = (const float*)d_in[i]; break;
            case BB * SS * 2:    idx = d_in[i];               break;
            case DD * DD:        W   = (const float*)d_in[i]; break;
            case DD:             bia = (const float*)d_in[i]; break;
            default: break;
        }
    }

    float *p_s, *g_s, *part_s;
    cudaGetSymbolAddress((void**)&p_s, g_p);
    cudaGetSymbolAddress((void**)&g_s, g_g);
    cudaGetSymbolAddress((void**)&part_s, g_part);

    // span decode (tiny)
    init_kernel<<<1, 1>>>();
    decode_kernel<<<NSPAN / 256, 256>>>((const int*)idx);

    // main pipeline
    dim3 gemm_grid(MM / BM, DD / BN);
    gemm_tf32_kernel<<<gemm_grid, 256>>>(h, W, p_s);

    const int nscan = BB * NT * DD;
    prefix_partial_kernel<<<nscan / 256, 256>>>(p_s, part_s);
    prefix_scan_kernel<<<nscan / 256, 256>>>(p_s, part_s, g_s);

    // epilogues (blocks past the runtime counts exit immediately)
    epi_valid_kernel<<<NSPAN, 256>>>(g_s, bia, (float*)d_out);
    epi_invalid_kernel<<<NSPAN, 256>>>(bia, (float*)d_out);
}

// round 7
// speedup vs baseline: 1.2651x; 1.2651x over previous
#include <cuda_runtime.h>
#include <cstdint>

// Problem constants
#define BB   8
#define LL   512
#define DD   1024
#define SS   6144
#define MM   (BB * LL)     // 4096 GEMM rows
#define LP1  (LL + 1)      // 513 prefix rows
#define NT   8             // prefix tiles along t
#define TW   (LL / NT)     // 64 timesteps per tile

// Scratch (device globals: no allocation allowed)
__device__ float g_p[MM * DD];          // p = h @ W^T          (16 MB)
__device__ float g_g[BB * LP1 * DD];    // prefix sums of p     (16.8 MB)
__device__ float g_part[BB * NT * DD];  // per-tile partial sums (256 KB)
__device__ int   g_is32;                // span_idx dtype flag

// ---------------------------------------------------------------------------
// helpers
// ---------------------------------------------------------------------------
__device__ __forceinline__ float tf32rna(float x) {
    uint32_t u;
    asm("cvt.rna.tf32.f32 %0, %1;" : "=r"(u) : "f"(x));
    return __uint_as_float(u);
}

__device__ __forceinline__ void mma_tf32(float c[4], const uint32_t a[4], const uint32_t b[2]) {
    asm volatile(
        "mma.sync.aligned.m16n8k8.row.col.f32.tf32.tf32.f32 "
        "{%0,%1,%2,%3}, {%4,%5,%6,%7}, {%8,%9}, {%0,%1,%2,%3};"
        : "+f"(c[0]), "+f"(c[1]), "+f"(c[2]), "+f"(c[3])
        : "r"(a[0]), "r"(a[1]), "r"(a[2]), "r"(a[3]),
          "r"(b[0]), "r"(b[1]));
}

// ---------------------------------------------------------------------------
// Kernel 1: GEMM (unchanged known-good version, 65.6us)
// 128x128x32 tile, 256 threads, register-staged prefetch, cvt.rna at STS,
// KPAD=36 conflict-free.
// ---------------------------------------------------------------------------
#define BM 128
#define BN 128
#define BK 32
#define KPAD 36

__global__ void __launch_bounds__(256)
gemm_tf32_kernel(const float* __restrict__ A,
                 const float* __restrict__ Wm,
                 float* __restrict__ P)
{
    __shared__ float As[BM * KPAD];
    __shared__ float Bs[BN * KPAD];

    const int tid  = threadIdx.x;
    const int warp = tid >> 5;
    const int lane = tid & 31;
    const int wm   = warp >> 1;
    const int wn   = warp & 1;
    const int m0   = blockIdx.x * BM;
    const int n0   = blockIdx.y * BN;

    const int lr = tid >> 3;
    const int lc = (tid & 7) * 4;

    const float* Ag = A  + (size_t)(m0 + lr) * DD + lc;
    const float* Bg = Wm + (size_t)(n0 + lr) * DD + lc;

    float acc[2][8][4];
    #pragma unroll
    for (int mt = 0; mt < 2; mt++)
        #pragma unroll
        for (int nt = 0; nt < 8; nt++)
            #pragma unroll
            for (int r = 0; r < 4; r++) acc[mt][nt][r] = 0.0f;

    float4 ra[4], rb[4];
    #pragma unroll
    for (int j = 0; j < 4; j++) {
        ra[j] = *(const float4*)(Ag + (size_t)j * 32 * DD);
        rb[j] = *(const float4*)(Bg + (size_t)j * 32 * DD);
    }

    const int NKT = DD / BK;
    for (int kt = 0; kt < NKT; kt++) {
        #pragma unroll
        for (int j = 0; j < 4; j++) {
            float4 a = ra[j], b = rb[j];
            a.x = tf32rna(a.x); a.y = tf32rna(a.y); a.z = tf32rna(a.z); a.w = tf32rna(a.w);
            b.x = tf32rna(b.x); b.y = tf32rna(b.y); b.z = tf32rna(b.z); b.w = tf32rna(b.w);
            *(float4*)(&As[(lr + j * 32) * KPAD + lc]) = a;
            *(float4*)(&Bs[(lr + j * 32) * KPAD + lc]) = b;
        }
        __syncthreads();

        if (kt + 1 < NKT) {
            const int ko = (kt + 1) * BK;
            #pragma unroll
            for (int j = 0; j < 4; j++) {
                ra[j] = *(const float4*)(Ag + (size_t)j * 32 * DD + ko);
                rb[j] = *(const float4*)(Bg + (size_t)j * 32 * DD + ko);
            }
        }

        #pragma unroll
        for (int ks = 0; ks < 4; ks++) {
            const int k0 = ks * 8 + (lane & 3);
            const int rA = wm * 32 + (lane >> 2);

            uint32_t af[2][4];
            #pragma unroll
            for (int mt = 0; mt < 2; mt++) {
                const int r = rA + mt * 16;
                af[mt][0] = __float_as_uint(As[r       * KPAD + k0]);
                af[mt][1] = __float_as_uint(As[(r + 8) * KPAD + k0]);
                af[mt][2] = __float_as_uint(As[r       * KPAD + k0 + 4]);
                af[mt][3] = __float_as_uint(As[(r + 8) * KPAD + k0 + 4]);
            }
            uint32_t bf[8][2];
            #pragma unroll
            for (int nt = 0; nt < 8; nt++) {
                const int n = wn * 64 + nt * 8 + (lane >> 2);
                bf[nt][0] = __float_as_uint(Bs[n * KPAD + k0]);
                bf[nt][1] = __float_as_uint(Bs[n * KPAD + k0 + 4]);
            }
            #pragma unroll
            for (int mt = 0; mt < 2; mt++)
                #pragma unroll
                for (int nt = 0; nt < 8; nt++)
                    mma_tf32(acc[mt][nt], af[mt], bf[nt]);
        }
        __syncthreads();
    }

    const int mrow = m0 + wm * 32 + (lane >> 2);
    const int ncol = n0 + wn * 64 + (lane & 3) * 2;
    #pragma unroll
    for (int mt = 0; mt < 2; mt++) {
        #pragma unroll
        for (int nt = 0; nt < 8; nt++) {
            const int r = mrow + mt * 16;
            const int c = ncol + nt * 8;
            *(float2*)(&P[(size_t)r       * DD + c]) = make_float2(acc[mt][nt][0], acc[mt][nt][1]);
            *(float2*)(&P[(size_t)(r + 8) * DD + c]) = make_float2(acc[mt][nt][2], acc[mt][nt][3]);
        }
    }
}

// ---------------------------------------------------------------------------
// Kernel 2a: per-tile partial sums (65536 threads) + dtype detection.
// ---------------------------------------------------------------------------
__global__ void __launch_bounds__(256)
prefix_partial_kernel(const float* __restrict__ P,
                      float* __restrict__ part,
                      const int* __restrict__ idx_words)
{
    if (blockIdx.x == 0 && threadIdx.x == 0) {
        // int64: odd 32-bit words are the zero high halves of values < 512.
        // int32: odd words are 'end' values -- 64 zeros is impossible.
        int any = 0;
        #pragma unroll
        for (int j = 0; j < 64; j++) any |= idx_words[2 * j + 1];
        g_is32 = (any != 0) ? 1 : 0;
    }

    const int gidx = blockIdx.x * blockDim.x + threadIdx.x;
    const int e    = gidx & (DD - 1);
    const int tile = (gidx >> 10) & (NT - 1);
    const int b    = gidx >> 13;

    const float* p = P + ((size_t)b * LL + tile * TW) * DD + e;
    float s = 0.0f;
    #pragma unroll
    for (int j = 0; j < TW; j++) s += p[(size_t)j * DD];
    part[((size_t)b * NT + tile) * DD + e] = s;
}

// ---------------------------------------------------------------------------
// Kernel 2b: scan within tile using tile offsets.
// ---------------------------------------------------------------------------
__global__ void __launch_bounds__(256)
prefix_scan_kernel(const float* __restrict__ P,
                   const float* __restrict__ part,
                   float* __restrict__ G)
{
    const int gidx = blockIdx.x * blockDim.x + threadIdx.x;
    const int e    = gidx & (DD - 1);
    const int tile = (gidx >> 10) & (NT - 1);
    const int b    = gidx >> 13;

    float c = 0.0f;
    for (int t = 0; t < tile; t++)
        c += part[((size_t)b * NT + t) * DD + e];

    const float* p = P + ((size_t)b * LL + tile * TW) * DD + e;
    float*       g = G + ((size_t)b * LP1 + tile * TW) * DD + e;

    if (tile == 0) g[0] = 0.0f;

    #pragma unroll 8
    for (int j = 0; j < TW; j++) {
        c += p[(size_t)j * DD];
        g[(size_t)(j + 1) * DD] = c;
    }
}

// ---------------------------------------------------------------------------
// Kernel 3: epilogue. One block (256 thr) per span.
// Valid:   out = relu((g[ge] - g[gs]) * inv + bias)
// Invalid: out = relu(bias)  -- NO G reads (saves ~200MB of L2 traffic).
// ---------------------------------------------------------------------------
__global__ void __launch_bounds__(256)
epilogue_kernel(const int* __restrict__ idx_words,
                const float* __restrict__ G,
                const float* __restrict__ bias,
                float* __restrict__ out)
{
    const int span = blockIdx.x;          // 0 .. B*S-1
    const int d    = threadIdx.x * 4;

    int w0, w1;
    if (g_is32) {
        w0 = idx_words[2 * span];
        w1 = idx_words[2 * span + 1];
    } else {
        w0 = idx_words[4 * span];
        w1 = idx_words[4 * span + 2];
    }
    const int s0 = min(max(w0, 0), LL - 1);
    const int e0 = min(max(w1, 0), LL - 1);

    float4 bb = *(const float4*)(bias + d);
    float4 o;

    if (s0 <= e0) {
        const int b = span / SS;
        const float inv = 1.0f / (float)(e0 - s0 + 1);
        const float* gs = G + ((size_t)b * LP1 + s0)     * DD;
        const float* ge = G + ((size_t)b * LP1 + e0 + 1) * DD;

        float4 a = *(const float4*)(ge + d);
        float4 c = *(const float4*)(gs + d);
        o.x = fmaxf(fmaf(a.x - c.x, inv, bb.x), 0.0f);
        o.y = fmaxf(fmaf(a.y - c.y, inv, bb.y), 0.0f);
        o.z = fmaxf(fmaf(a.z - c.z, inv, bb.z), 0.0f);
        o.w = fmaxf(fmaf(a.w - c.w, inv, bb.w), 0.0f);
    } else {
        o.x = fmaxf(bb.x, 0.0f);
        o.y = fmaxf(bb.y, 0.0f);
        o.z = fmaxf(bb.z, 0.0f);
        o.w = fmaxf(bb.w, 0.0f);
    }

    *(float4*)(out + (size_t)span * DD + d) = o;
}

// ---------------------------------------------------------------------------
// launch
// ---------------------------------------------------------------------------
extern "C" void kernel_launch(void* const* d_in, const int* in_sizes, int n_in,
                              void* d_out, int out_size)
{
    const float* h   = nullptr;
    const void*  idx = nullptr;
    const float* W   = nullptr;
    const float* bia = nullptr;
    for (int i = 0; i < n_in; i++) {
        switch (in_sizes[i]) {
            case BB * LL * DD:   h   = (const float*)d_in[i]; break;
            case BB * SS * 2:    idx = d_in[i];               break;
            case DD * DD:        W   = (const float*)d_in[i]; break;
            case DD:             bia = (const float*)d_in[i]; break;
            default: break;
        }
    }

    float *p_s, *g_s, *part_s;
    cudaGetSymbolAddress((void**)&p_s, g_p);
    cudaGetSymbolAddress((void**)&g_s, g_g);
    cudaGetSymbolAddress((void**)&part_s, g_part);

    dim3 gemm_grid(MM / BM, DD / BN);
    gemm_tf32_kernel<<<gemm_grid, 256>>>(h, W, p_s);

    const int nscan = BB * NT * DD;    // 65536
    prefix_partial_kernel<<<nscan / 256, 256>>>(p_s, part_s, (const int*)idx);
    prefix_scan_kernel<<<nscan / 256, 256>>>(p_s, part_s, g_s);

    epilogue_kernel<<<BB * SS, 256>>>((const int*)idx, g_s, bia, (float*)d_out);
}

// round 9
// speedup vs baseline: 1.5148x; 1.1974x over previous
#include <cuda_runtime.h>
#include <cuda_fp16.h>
#include <cstdint>

// Problem constants
#define BB   8
#define LL   512
#define DD   1024
#define SS   6144
#define MM   (BB * LL)     // 4096 GEMM rows
#define LP1  (LL + 1)      // 513 prefix rows
#define NT   8             // prefix tiles along t
#define TW   (LL / NT)     // 64 timesteps per tile

// Scratch (device globals: no allocation allowed)
__device__ float g_p[MM * DD];          // p = h @ W^T          (16 MB)
__device__ float g_g[BB * LP1 * DD];    // prefix sums of p     (16.8 MB)
__device__ float g_part[BB * NT * DD];  // per-tile partial sums (256 KB)
__device__ int   g_is32;                // span_idx dtype flag

// ---------------------------------------------------------------------------
// helpers
// ---------------------------------------------------------------------------
__device__ __forceinline__ void mma_f16(float c[4], const uint32_t a[4], const uint32_t b[2]) {
    asm volatile(
        "mma.sync.aligned.m16n8k16.row.col.f32.f16.f16.f32 "
        "{%0,%1,%2,%3}, {%4,%5,%6,%7}, {%8,%9}, {%0,%1,%2,%3};"
        : "+f"(c[0]), "+f"(c[1]), "+f"(c[2]), "+f"(c[3])
        : "r"(a[0]), "r"(a[1]), "r"(a[2]), "r"(a[3]),
          "r"(b[0]), "r"(b[1]));
}

__device__ __forceinline__ uint32_t pack_half2(float x, float y) {
    __half2 h = __float22half2_rn(make_float2(x, y));
    return *reinterpret_cast<uint32_t*>(&h);
}

// ---------------------------------------------------------------------------
// Kernel 1: p[m][n] = sum_d h[m][d] * W[n][d]   (fp16 tensor-core GEMM,
// fp32 accumulate). 128x128x32 block tile, 256 threads (8 warps, 4x2),
// warp tile 32x64, m16n8k16 MMA. Register-staged prefetch; float->half
// conversion at STS time. KPH=40 halves row stride: conflict-free fragment LDS.
// 2 CTAs/SM (20.5KB smem) -> whole 256-CTA grid is one wave on 148 SMs.
// ---------------------------------------------------------------------------
#define BM 128
#define BN 128
#define BK 32
#define KPH 40          // padded row stride in halves

__global__ void __launch_bounds__(256, 2)
gemm_f16_kernel(const float* __restrict__ A,   // h  [4096,1024]
                const float* __restrict__ Wm,  // W  [1024,1024]
                float* __restrict__ P)         // p  [4096,1024]
{
    __shared__ __half As[BM * KPH];
    __shared__ __half Bs[BN * KPH];

    const int tid  = threadIdx.x;
    const int warp = tid >> 5;
    const int lane = tid & 31;
    const int wm   = warp >> 1;   // 0..3
    const int wn   = warp & 1;    // 0..1
    const int m0   = blockIdx.x * BM;
    const int n0   = blockIdx.y * BN;

    // gmem->smem: thread handles rows (tid>>3)+{0,32,64,96}, float4 col (tid&7)
    const int lr = tid >> 3;
    const int lc = (tid & 7) * 4;

    const float* Ag = A  + (size_t)(m0 + lr) * DD + lc;
    const float* Bg = Wm + (size_t)(n0 + lr) * DD + lc;

    float acc[2][8][4];
    #pragma unroll
    for (int mt = 0; mt < 2; mt++)
        #pragma unroll
        for (int nt = 0; nt < 8; nt++)
            #pragma unroll
            for (int r = 0; r < 4; r++) acc[mt][nt][r] = 0.0f;

    float4 ra[4], rb[4];
    #pragma unroll
    for (int j = 0; j < 4; j++) {
        ra[j] = *(const float4*)(Ag + (size_t)j * 32 * DD);
        rb[j] = *(const float4*)(Bg + (size_t)j * 32 * DD);
    }

    const int NKT = DD / BK;  // 32
    for (int kt = 0; kt < NKT; kt++) {
        // convert + store staged tile to smem (4 halves = 8B per store)
        #pragma unroll
        for (int j = 0; j < 4; j++) {
            float4 a = ra[j], b = rb[j];
            uint2 pa, pb;
            pa.x = pack_half2(a.x, a.y); pa.y = pack_half2(a.z, a.w);
            pb.x = pack_half2(b.x, b.y); pb.y = pack_half2(b.z, b.w);
            *(uint2*)(&As[(lr + j * 32) * KPH + lc]) = pa;
            *(uint2*)(&Bs[(lr + j * 32) * KPH + lc]) = pb;
        }
        __syncthreads();

        // prefetch next K-tile while computing this one
        if (kt + 1 < NKT) {
            const int ko = (kt + 1) * BK;
            #pragma unroll
            for (int j = 0; j < 4; j++) {
                ra[j] = *(const float4*)(Ag + (size_t)j * 32 * DD + ko);
                rb[j] = *(const float4*)(Bg + (size_t)j * 32 * DD + ko);
            }
        }

        #pragma unroll
        for (int ks = 0; ks < 2; ks++) {            // two K=16 steps per chunk
            const int kb = ks * 16 + (lane & 3) * 2; // half index within row
            const int rA = wm * 32 + (lane >> 2);

            uint32_t af[2][4];
            #pragma unroll
            for (int mt = 0; mt < 2; mt++) {
                const int r = rA + mt * 16;
                af[mt][0] = *(const uint32_t*)(&As[r       * KPH + kb]);
                af[mt][1] = *(const uint32_t*)(&As[(r + 8) * KPH + kb]);
                af[mt][2] = *(const uint32_t*)(&As[r       * KPH + kb + 8]);
                af[mt][3] = *(const uint32_t*)(&As[(r + 8) * KPH + kb + 8]);
            }
            uint32_t bf[8][2];
            #pragma unroll
            for (int nt = 0; nt < 8; nt++) {
                const int n = wn * 64 + nt * 8 + (lane >> 2);
                bf[nt][0] = *(const uint32_t*)(&Bs[n * KPH + kb]);
                bf[nt][1] = *(const uint32_t*)(&Bs[n * KPH + kb + 8]);
            }
            #pragma unroll
            for (int mt = 0; mt < 2; mt++)
                #pragma unroll
                for (int nt = 0; nt < 8; nt++)
                    mma_f16(acc[mt][nt], af[mt], bf[nt]);
        }
        __syncthreads();
    }

    // epilogue: write p (same fragment->gmem mapping as m16n8k8)
    const int mrow = m0 + wm * 32 + (lane >> 2);
    const int ncol = n0 + wn * 64 + (lane & 3) * 2;
    #pragma unroll
    for (int mt = 0; mt < 2; mt++) {
        #pragma unroll
        for (int nt = 0; nt < 8; nt++) {
            const int r = mrow + mt * 16;
            const int c = ncol + nt * 8;
            *(float2*)(&P[(size_t)r       * DD + c]) = make_float2(acc[mt][nt][0], acc[mt][nt][1]);
            *(float2*)(&P[(size_t)(r + 8) * DD + c]) = make_float2(acc[mt][nt][2], acc[mt][nt][3]);
        }
    }
}

// ---------------------------------------------------------------------------
// Kernel 2a: per-tile partial sums (65536 threads) + dtype detection.
// ---------------------------------------------------------------------------
__global__ void __launch_bounds__(256)
prefix_partial_kernel(const float* __restrict__ P,
                      float* __restrict__ part,
                      const int* __restrict__ idx_words)
{
    if (blockIdx.x == 0 && threadIdx.x == 0) {
        // int64: odd 32-bit words are the zero high halves of values < 512.
        // int32: odd words are 'end' values -- 64 zeros is impossible.
        int any = 0;
        #pragma unroll
        for (int j = 0; j < 64; j++) any |= idx_words[2 * j + 1];
        g_is32 = (any != 0) ? 1 : 0;
    }

    const int gidx = blockIdx.x * blockDim.x + threadIdx.x;
    const int e    = gidx & (DD - 1);
    const int tile = (gidx >> 10) & (NT - 1);
    const int b    = gidx >> 13;

    const float* p = P + ((size_t)b * LL + tile * TW) * DD + e;
    float s = 0.0f;
    #pragma unroll
    for (int j = 0; j < TW; j++) s += p[(size_t)j * DD];
    part[((size_t)b * NT + tile) * DD + e] = s;
}

// ---------------------------------------------------------------------------
// Kernel 2b: scan within tile using tile offsets.
// ---------------------------------------------------------------------------
__global__ void __launch_bounds__(256)
prefix_scan_kernel(const float* __restrict__ P,
                   const float* __restrict__ part,
                   float* __restrict__ G)
{
    const int gidx = blockIdx.x * blockDim.x + threadIdx.x;
    const int e    = gidx & (DD - 1);
    const int tile = (gidx >> 10) & (NT - 1);
    const int b    = gidx >> 13;

    float c = 0.0f;
    for (int t = 0; t < tile; t++)
        c += part[((size_t)b * NT + t) * DD + e];

    const float* p = P + ((size_t)b * LL + tile * TW) * DD + e;
    float*       g = G + ((size_t)b * LP1 + tile * TW) * DD + e;

    if (tile == 0) g[0] = 0.0f;

    #pragma unroll 8
    for (int j = 0; j < TW; j++) {
        c += p[(size_t)j * DD];
        g[(size_t)(j + 1) * DD] = c;
    }
}

// ---------------------------------------------------------------------------
// Kernel 3: epilogue (R7 known-good). One block (256 thr) per span.
// Valid:   out = relu((g[ge] - g[gs]) * inv + bias)
// Invalid: out = relu(bias)  -- no G reads.
// ---------------------------------------------------------------------------
__global__ void __launch_bounds__(256)
epilogue_kernel(const int* __restrict__ idx_words,
                const float* __restrict__ G,
                const float* __restrict__ bias,
                float* __restrict__ out)
{
    const int span = blockIdx.x;          // 0 .. B*S-1
    const int d    = threadIdx.x * 4;

    int w0, w1;
    if (g_is32) {
        w0 = idx_words[2 * span];
        w1 = idx_words[2 * span + 1];
    } else {
        w0 = idx_words[4 * span];
        w1 = idx_words[4 * span + 2];
    }
    const int s0 = min(max(w0, 0), LL - 1);
    const int e0 = min(max(w1, 0), LL - 1);

    float4 bb = *(const float4*)(bias + d);
    float4 o;

    if (s0 <= e0) {
        const int b = span / SS;
        const float inv = 1.0f / (float)(e0 - s0 + 1);
        const float* gs = G + ((size_t)b * LP1 + s0)     * DD;
        const float* ge = G + ((size_t)b * LP1 + e0 + 1) * DD;

        float4 a = *(const float4*)(ge + d);
        float4 c = *(const float4*)(gs + d);
        o.x = fmaxf(fmaf(a.x - c.x, inv, bb.x), 0.0f);
        o.y = fmaxf(fmaf(a.y - c.y, inv, bb.y), 0.0f);
        o.z = fmaxf(fmaf(a.z - c.z, inv, bb.z), 0.0f);
        o.w = fmaxf(fmaf(a.w - c.w, inv, bb.w), 0.0f);
    } else {
        o.x = fmaxf(bb.x, 0.0f);
        o.y = fmaxf(bb.y, 0.0f);
        o.z = fmaxf(bb.z, 0.0f);
        o.w = fmaxf(bb.w, 0.0f);
    }

    *(float4*)(out + (size_t)span * DD + d) = o;
}

// ---------------------------------------------------------------------------
// launch
// ---------------------------------------------------------------------------
extern "C" void kernel_launch(void* const* d_in, const int* in_sizes, int n_in,
                              void* d_out, int out_size)
{
    const float* h   = nullptr;
    const void*  idx = nullptr;
    const float* W   = nullptr;
    const float* bia = nullptr;
    for (int i = 0; i < n_in; i++) {
        switch (in_sizes[i]) {
            case BB * LL * DD:   h   = (const float*)d_in[i]; break;
            case BB * SS * 2:    idx = d_in[i];               break;
            case DD * DD:        W   = (const float*)d_in[i]; break;
            case DD:             bia = (const float*)d_in[i]; break;
            default: break;
        }
    }

    float *p_s, *g_s, *part_s;
    cudaGetSymbolAddress((void**)&p_s, g_p);
    cudaGetSymbolAddress((void**)&g_s, g_g);
    cudaGetSymbolAddress((void**)&part_s, g_part);

    dim3 gemm_grid(MM / BM, DD / BN);  // 32 x 8
    gemm_f16_kernel<<<gemm_grid, 256>>>(h, W, p_s);

    const int nscan = BB * NT * DD;    // 65536
    prefix_partial_kernel<<<nscan / 256, 256>>>(p_s, part_s, (const int*)idx);
    prefix_scan_kernel<<<nscan / 256, 256>>>(p_s, part_s, g_s);

    epilogue_kernel<<<BB * SS, 256>>>((const int*)idx, g_s, bia, (float*)d_out);
}

// round 10
// speedup vs baseline: 1.6761x; 1.1065x over previous
#include <cuda_runtime.h>
#include <cuda_fp16.h>
#include <cstdint>

// Problem constants
#define BB   8
#define LL   512
#define DD   1024
#define SS   6144
#define MM   (BB * LL)     // 4096 GEMM rows
#define LP1  (LL + 1)      // 513 prefix rows
#define NT   8             // prefix tiles along t
#define TW   (LL / NT)     // 64 timesteps per tile

// Scratch (device globals: no allocation allowed)
__device__ float g_p[MM * DD];          // p = h @ W^T          (16 MB)
__device__ float g_g[BB * LP1 * DD];    // prefix sums of p     (16.8 MB)
__device__ float g_part[BB * NT * DD];  // per-tile partial sums (256 KB)
__device__ int   g_is32;                // span_idx dtype flag

// ---------------------------------------------------------------------------
// helpers
// ---------------------------------------------------------------------------
__device__ __forceinline__ void mma_f16(float c[4], const uint32_t a[4], const uint32_t b[2]) {
    asm volatile(
        "mma.sync.aligned.m16n8k16.row.col.f32.f16.f16.f32 "
        "{%0,%1,%2,%3}, {%4,%5,%6,%7}, {%8,%9}, {%0,%1,%2,%3};"
        : "+f"(c[0]), "+f"(c[1]), "+f"(c[2]), "+f"(c[3])
        : "r"(a[0]), "r"(a[1]), "r"(a[2]), "r"(a[3]),
          "r"(b[0]), "r"(b[1]));
}

__device__ __forceinline__ uint32_t pack_half2(float x, float y) {
    __half2 h = __float22half2_rn(make_float2(x, y));
    return *reinterpret_cast<uint32_t*>(&h);
}

// ---------------------------------------------------------------------------
// Kernel 1: p[m][n] = sum_d h[m][d] * W[n][d]   (fp16 MMA, fp32 accumulate)
// 128x256x32 block tile, 256 threads (8 warps as 2x4), 64x64 warp tiles.
// 64x64 warp tile gives 16.4 MACs per LDS byte (vs 10.9 at 32x64): fragment
// smem traffic no longer starves HMMA. Register-staged gmem prefetch;
// fp32->fp16 at STS time. KPH=40 half-stride: conflict-free fragment LDS.
// Grid 32x4 = 128 CTAs, one wave.
// ---------------------------------------------------------------------------
#define BM 128
#define BN 256
#define BK 32
#define KPH 40          // padded row stride in halves

__global__ void __launch_bounds__(256, 1)
gemm_f16_kernel(const float* __restrict__ A,   // h  [4096,1024]
                const float* __restrict__ Wm,  // W  [1024,1024]
                float* __restrict__ P)         // p  [4096,1024]
{
    __shared__ __half As[BM * KPH];   // 10 KB
    __shared__ __half Bs[BN * KPH];   // 20 KB

    const int tid  = threadIdx.x;
    const int warp = tid >> 5;
    const int lane = tid & 31;
    const int wm   = warp >> 2;   // 0..1  (64-row slab)
    const int wn   = warp & 3;    // 0..3  (64-col slab)
    const int m0   = blockIdx.x * BM;
    const int n0   = blockIdx.y * BN;

    // gmem->smem loader lanes: row = (tid>>3) + j*32, float4 col (tid&7)
    const int lr = tid >> 3;
    const int lc = (tid & 7) * 4;

    const float* Ag = A  + (size_t)(m0 + lr) * DD + lc;
    const float* Bg = Wm + (size_t)(n0 + lr) * DD + lc;

    float acc[4][8][4];
    #pragma unroll
    for (int mt = 0; mt < 4; mt++)
        #pragma unroll
        for (int nt = 0; nt < 8; nt++)
            #pragma unroll
            for (int r = 0; r < 4; r++) acc[mt][nt][r] = 0.0f;

    float4 ra[4], rb[8];
    #pragma unroll
    for (int j = 0; j < 4; j++)
        ra[j] = *(const float4*)(Ag + (size_t)j * 32 * DD);
    #pragma unroll
    for (int j = 0; j < 8; j++)
        rb[j] = *(const float4*)(Bg + (size_t)j * 32 * DD);

    const int NKT = DD / BK;  // 32
    for (int kt = 0; kt < NKT; kt++) {
        // convert + store staged tile to smem
        #pragma unroll
        for (int j = 0; j < 4; j++) {
            float4 a = ra[j];
            uint2 pa;
            pa.x = pack_half2(a.x, a.y); pa.y = pack_half2(a.z, a.w);
            *(uint2*)(&As[(lr + j * 32) * KPH + lc]) = pa;
        }
        #pragma unroll
        for (int j = 0; j < 8; j++) {
            float4 b = rb[j];
            uint2 pb;
            pb.x = pack_half2(b.x, b.y); pb.y = pack_half2(b.z, b.w);
            *(uint2*)(&Bs[(lr + j * 32) * KPH + lc]) = pb;
        }
        __syncthreads();

        // prefetch next K-tile while computing this one
        if (kt + 1 < NKT) {
            const int ko = (kt + 1) * BK;
            #pragma unroll
            for (int j = 0; j < 4; j++)
                ra[j] = *(const float4*)(Ag + (size_t)j * 32 * DD + ko);
            #pragma unroll
            for (int j = 0; j < 8; j++)
                rb[j] = *(const float4*)(Bg + (size_t)j * 32 * DD + ko);
        }

        #pragma unroll
        for (int ks = 0; ks < 2; ks++) {             // two K=16 steps per chunk
            const int kb = ks * 16 + (lane & 3) * 2; // half index within row
            const int rA = wm * 64 + (lane >> 2);

            uint32_t af[4][4];
            #pragma unroll
            for (int mt = 0; mt < 4; mt++) {
                const int r = rA + mt * 16;
                af[mt][0] = *(const uint32_t*)(&As[r       * KPH + kb]);
                af[mt][1] = *(const uint32_t*)(&As[(r + 8) * KPH + kb]);
                af[mt][2] = *(const uint32_t*)(&As[r       * KPH + kb + 8]);
                af[mt][3] = *(const uint32_t*)(&As[(r + 8) * KPH + kb + 8]);
            }
            uint32_t bf[8][2];
            #pragma unroll
            for (int nt = 0; nt < 8; nt++) {
                const int n = wn * 64 + nt * 8 + (lane >> 2);
                bf[nt][0] = *(const uint32_t*)(&Bs[n * KPH + kb]);
                bf[nt][1] = *(const uint32_t*)(&Bs[n * KPH + kb + 8]);
            }
            #pragma unroll
            for (int mt = 0; mt < 4; mt++)
                #pragma unroll
                for (int nt = 0; nt < 8; nt++)
                    mma_f16(acc[mt][nt], af[mt], bf[nt]);
        }
        __syncthreads();
    }

    // epilogue: write p
    const int mrow = m0 + wm * 64 + (lane >> 2);
    const int ncol = n0 + wn * 64 + (lane & 3) * 2;
    #pragma unroll
    for (int mt = 0; mt < 4; mt++) {
        #pragma unroll
        for (int nt = 0; nt < 8; nt++) {
            const int r = mrow + mt * 16;
            const int c = ncol + nt * 8;
            *(float2*)(&P[(size_t)r       * DD + c]) = make_float2(acc[mt][nt][0], acc[mt][nt][1]);
            *(float2*)(&P[(size_t)(r + 8) * DD + c]) = make_float2(acc[mt][nt][2], acc[mt][nt][3]);
        }
    }
}

// ---------------------------------------------------------------------------
// Kernel 2a: per-tile partial sums (65536 threads) + dtype detection.
// ---------------------------------------------------------------------------
__global__ void __launch_bounds__(256)
prefix_partial_kernel(const float* __restrict__ P,
                      float* __restrict__ part,
                      const int* __restrict__ idx_words)
{
    if (blockIdx.x == 0 && threadIdx.x == 0) {
        // int64: odd 32-bit words are the zero high halves of values < 512.
        // int32: odd words are 'end' values -- 64 zeros is impossible.
        int any = 0;
        #pragma unroll
        for (int j = 0; j < 64; j++) any |= idx_words[2 * j + 1];
        g_is32 = (any != 0) ? 1 : 0;
    }

    const int gidx = blockIdx.x * blockDim.x + threadIdx.x;
    const int e    = gidx & (DD - 1);
    const int tile = (gidx >> 10) & (NT - 1);
    const int b    = gidx >> 13;

    const float* p = P + ((size_t)b * LL + tile * TW) * DD + e;
    float s = 0.0f;
    #pragma unroll
    for (int j = 0; j < TW; j++) s += p[(size_t)j * DD];
    part[((size_t)b * NT + tile) * DD + e] = s;
}

// ---------------------------------------------------------------------------
// Kernel 2b: scan within tile using tile offsets.
// ---------------------------------------------------------------------------
__global__ void __launch_bounds__(256)
prefix_scan_kernel(const float* __restrict__ P,
                   const float* __restrict__ part,
                   float* __restrict__ G)
{
    const int gidx = blockIdx.x * blockDim.x + threadIdx.x;
    const int e    = gidx & (DD - 1);
    const int tile = (gidx >> 10) & (NT - 1);
    const int b    = gidx >> 13;

    float c = 0.0f;
    for (int t = 0; t < tile; t++)
        c += part[((size_t)b * NT + t) * DD + e];

    const float* p = P + ((size_t)b * LL + tile * TW) * DD + e;
    float*       g = G + ((size_t)b * LP1 + tile * TW) * DD + e;

    if (tile == 0) g[0] = 0.0f;

    #pragma unroll 8
    for (int j = 0; j < TW; j++) {
        c += p[(size_t)j * DD];
        g[(size_t)(j + 1) * DD] = c;
    }
}

// ---------------------------------------------------------------------------
// Kernel 3: epilogue. One block (256 thr) per span.
// Valid:   out = relu((g[ge] - g[gs]) * inv + bias)
// Invalid: out = relu(bias)  -- no G reads.
// Output stored with .cs (evict-first) to protect the L2-resident G table.
// ---------------------------------------------------------------------------
__global__ void __launch_bounds__(256)
epilogue_kernel(const int* __restrict__ idx_words,
                const float* __restrict__ G,
                const float* __restrict__ bias,
                float* __restrict__ out)
{
    const int span = blockIdx.x;          // 0 .. B*S-1
    const int d    = threadIdx.x * 4;

    int w0, w1;
    if (g_is32) {
        w0 = idx_words[2 * span];
        w1 = idx_words[2 * span + 1];
    } else {
        w0 = idx_words[4 * span];
        w1 = idx_words[4 * span + 2];
    }
    const int s0 = min(max(w0, 0), LL - 1);
    const int e0 = min(max(w1, 0), LL - 1);

    float4 bb = *(const float4*)(bias + d);
    float4 o;

    if (s0 <= e0) {
        const int b = span / SS;
        const float inv = 1.0f / (float)(e0 - s0 + 1);
        const float* gs = G + ((size_t)b * LP1 + s0)     * DD;
        const float* ge = G + ((size_t)b * LP1 + e0 + 1) * DD;

        float4 a = *(const float4*)(ge + d);
        float4 c = *(const float4*)(gs + d);
        o.x = fmaxf(fmaf(a.x - c.x, inv, bb.x), 0.0f);
        o.y = fmaxf(fmaf(a.y - c.y, inv, bb.y), 0.0f);
        o.z = fmaxf(fmaf(a.z - c.z, inv, bb.z), 0.0f);
        o.w = fmaxf(fmaf(a.w - c.w, inv, bb.w), 0.0f);
    } else {
        o.x = fmaxf(bb.x, 0.0f);
        o.y = fmaxf(bb.y, 0.0f);
        o.z = fmaxf(bb.z, 0.0f);
        o.w = fmaxf(bb.w, 0.0f);
    }

    __stcs((float4*)(out + (size_t)span * DD + d), o);
}

// ---------------------------------------------------------------------------
// launch
// ---------------------------------------------------------------------------
extern "C" void kernel_launch(void* const* d_in, const int* in_sizes, int n_in,
                              void* d_out, int out_size)
{
    const float* h   = nullptr;
    const void*  idx = nullptr;
    const float* W   = nullptr;
    const float* bia = nullptr;
    for (int i = 0; i < n_in; i++) {
        switch (in_sizes[i]) {
            case BB * LL * DD:   h   = (const float*)d_in[i]; break;
            case BB * SS * 2:    idx = d_in[i];               break;
            case DD * DD:        W   = (const float*)d_in[i]; break;
            case DD:             bia = (const float*)d_in[i]; break;
            default: break;
        }
    }

    float *p_s, *g_s, *part_s;
    cudaGetSymbolAddress((void**)&p_s, g_p);
    cudaGetSymbolAddress((void**)&g_s, g_g);
    cudaGetSymbolAddress((void**)&part_s, g_part);

    dim3 gemm_grid(MM / BM, DD / BN);  // 32 x 4
    gemm_f16_kernel<<<gemm_grid, 256>>>(h, W, p_s);

    const int nscan = BB * NT * DD;    // 65536
    prefix_partial_kernel<<<nscan / 256, 256>>>(p_s, part_s, (const int*)idx);
    prefix_scan_kernel<<<nscan / 256, 256>>>(p_s, part_s, g_s);

    epilogue_kernel<<<BB * SS, 256>>>((const int*)idx, g_s, bia, (float*)d_out);
}